// round 9
// baseline (speedup 1.0000x reference)
#include <cuda_runtime.h>
#include <cstdint>

// FUSE hydrology bucket model scan — 2 units per thread to fill the
// program-order issue slots left idle by the loop-carried MUFU chain.
//
// forcing: (T,H,3) f32 (p=comp0, pet=comp1); out runoff: (T,H) f32.
// H=4096 units; each thread runs units h and h+2048 -> 64 warps, one
// per SM. Per unit-step chain:
//   FFMA.SAT -> LG2 -> FMUL -> FMNMX(blo) -> EX2 -> FFMA.SAT (~50 cyc);
// unit B's instruction stream interleaves into unit A's stall windows.

#define T_STEPS   8192
#define H_UNITS   4096
#define H_HALF    (H_UNITS / 2)
#define H3        (H_UNITS * 3)
#define LG2EPS    (-19.931568569324174f)   // log2(1e-6)
#define CHUNK     8
#define NCHUNK    8
#define NCHUNKS_T (T_STEPS / CHUNK)        // 1024
#define SLOT_F    96                       // floats per step slot (32 x 3)
#define RING_HALF (NCHUNK * CHUNK * SLOT_F) // 6144 floats = 24 KB

__device__ __forceinline__ float fast_lg2(float x) {
    float r;
    asm("lg2.approx.f32 %0, %1;" : "=f"(r) : "f"(x));
    return r;
}
__device__ __forceinline__ float fast_ex2(float x) {
    float r;
    asm("ex2.approx.f32 %0, %1;" : "=f"(r) : "f"(x));
    return r;
}
__device__ __forceinline__ float fma_sat(float a, float b, float c) {
    float r;
    asm("fma.rn.sat.f32 %0, %1, %2, %3;" : "=f"(r) : "f"(a), "f"(b), "f"(c));
    return r;
}

__device__ __forceinline__ void issue_chunk2(int c, bool ld_pred,
                                             const float* gA, const float* gB,
                                             unsigned ringA, unsigned ringB,
                                             int lane)
{
    const int slot = c & (NCHUNK - 1);
    if (ld_pred) {
        const float* ga = gA + (size_t)(c * CHUNK) * H3 + lane * 4;
        const float* gb = gB + (size_t)(c * CHUNK) * H3 + lane * 4;
        unsigned sa = ringA + (unsigned)(slot * CHUNK) * (SLOT_F * 4)
                      + (unsigned)lane * 16u;
        unsigned sb = ringB + (unsigned)(slot * CHUNK) * (SLOT_F * 4)
                      + (unsigned)lane * 16u;
#pragma unroll
        for (int j = 0; j < CHUNK; j++) {
            asm volatile("cp.async.cg.shared.global [%0], [%1], 16;"
                         :: "r"(sa + (unsigned)j * (SLOT_F * 4)),
                            "l"(ga + (size_t)j * H3) : "memory");
            asm volatile("cp.async.cg.shared.global [%0], [%1], 16;"
                         :: "r"(sb + (unsigned)j * (SLOT_F * 4)),
                            "l"(gb + (size_t)j * H3) : "memory");
        }
    }
    asm volatile("cp.async.commit_group;" ::: "memory");
}

__global__ void __launch_bounds__(32)
fuse_scan_kernel(const float* __restrict__ forcing,
                 const float* __restrict__ initial_state,
                 const float* __restrict__ raw_params,
                 const float* __restrict__ param_lower,
                 const float* __restrict__ param_upper,
                 float* __restrict__ out)
{
    __shared__ float ring[2 * RING_HALF];   // 48 KB

    const int lane = threadIdx.x;
    const int hA0  = blockIdx.x * 32;           // unit-set A warp base
    const int hA   = hA0 + lane;                // unit A
    const int hB   = hA + H_HALF;               // unit B
    const bool ld_pred = (lane < 24);

    const unsigned ringA = (unsigned)__cvta_generic_to_shared(ring);
    const unsigned ringB = ringA + RING_HALF * 4;

    // ---- Parameter transform for both units (accurate expf) ----
    float physA[6], physB[6];
#pragma unroll
    for (int i = 0; i < 6; i++) {
        float lo = param_lower[i];
        float hi = param_upper[i];
        float ra = raw_params[hA * 6 + i];
        float rb = raw_params[hB * 6 + i];
        physA[i] = lo + (hi - lo) * (1.0f / (1.0f + expf(-ra)));
        physB[i] = lo + (hi - lo) * (1.0f / (1.0f + expf(-rb)));
    }
    const float inv_m1A   = 1.0f / physA[0];
    const float inv_m2A   = 1.0f / physA[1];
    const float basertA   = physA[3];
    const float qbpA      = physA[4];
    const float bexpA     = physA[5];
    const float perc2A    = physA[2] * inv_m2A;
    const float base2A    = basertA  * inv_m2A;
    const float blo1A     = bexpA * LG2EPS;
    const float blo2A     = qbpA  * LG2EPS;
    const float om_perc1A = 1.0f - physA[2] * inv_m1A;

    const float inv_m1B   = 1.0f / physB[0];
    const float inv_m2B   = 1.0f / physB[1];
    const float basertB   = physB[3];
    const float qbpB      = physB[4];
    const float bexpB     = physB[5];
    const float perc2B    = physB[2] * inv_m2B;
    const float base2B    = basertB  * inv_m2B;
    const float blo1B     = bexpB * LG2EPS;
    const float blo2B     = qbpB  * LG2EPS;
    const float om_perc1B = 1.0f - physB[2] * inv_m1B;

    float u1A = initial_state[hA * 2 + 0] * inv_m1A;
    float u2A = initial_state[hA * 2 + 1] * inv_m2A;
    float u1B = initial_state[hB * 2 + 0] * inv_m1B;
    float u2B = initial_state[hB * 2 + 1] * inv_m2B;

    const float* gA = forcing + (size_t)hA0 * 3;
    const float* gB = forcing + (size_t)(hA0 + H_HALF) * 3;

#define PROCESS2(C, SAFE)                                                   \
    do {                                                                    \
        const int _slot = (C) & (NCHUNK - 1);                               \
        const float* _sa = ring + (_slot * CHUNK) * SLOT_F + lane * 3;      \
        const float* _sb = _sa + RING_HALF;                                 \
        float* _opA = out + (size_t)(C) * CHUNK * H_UNITS + hA;             \
        float* _opB = out + (size_t)(C) * CHUNK * H_UNITS + hB;             \
        float _pA[CHUNK], _eA[CHUNK], _pB[CHUNK], _eB[CHUNK];               \
        _Pragma("unroll")                                                   \
        for (int _j = 0; _j < CHUNK; _j++) {                                \
            _pA[_j] = _sa[_j * SLOT_F + 0];                                 \
            _eA[_j] = _sa[_j * SLOT_F + 1];                                 \
            _pB[_j] = _sb[_j * SLOT_F + 0];                                 \
            _eB[_j] = _sb[_j * SLOT_F + 1];                                 \
        }                                                                   \
        _Pragma("unroll")                                                   \
        for (int _j = 0; _j < CHUNK; _j++) {                                \
            /* unit A */                                                    \
            const float pA   = _pA[_j];                                     \
            const float ppA  = pA * inv_m1A;                                \
            const float omcA = fmaf(-_eA[_j], inv_m1A, om_perc1A);          \
            const float x2A  = (SAFE) ? fminf(u2A, 1.0f) : u2A;             \
            const float a1A  = fmaxf(bexpA * fast_lg2(u1A), blo1A);         \
            const float a2A  = fmaxf(qbpA  * fast_lg2(x2A), blo2A);         \
            const float pw1A = fast_ex2(a1A);                               \
            const float pw2A = fast_ex2(a2A);                               \
            const float t1A  = fmaf(u1A, omcA, ppA);                        \
            const float t2A  = fmaf(perc2A, u1A, u2A);                      \
            u1A = fma_sat(-ppA,   pw1A, t1A);                               \
            u2A = fma_sat(-base2A, pw2A, t2A);                              \
            _opA[_j * H_UNITS] = fmaf(pA, pw1A, basertA * pw2A);            \
            /* unit B */                                                    \
            const float pB   = _pB[_j];                                     \
            const float ppB  = pB * inv_m1B;                                \
            const float omcB = fmaf(-_eB[_j], inv_m1B, om_perc1B);          \
            const float x2B  = (SAFE) ? fminf(u2B, 1.0f) : u2B;             \
            const float a1B  = fmaxf(bexpB * fast_lg2(u1B), blo1B);         \
            const float a2B  = fmaxf(qbpB  * fast_lg2(x2B), blo2B);         \
            const float pw1B = fast_ex2(a1B);                               \
            const float pw2B = fast_ex2(a2B);                               \
            const float t1B  = fmaf(u1B, omcB, ppB);                        \
            const float t2B  = fmaf(perc2B, u1B, u2B);                      \
            u1B = fma_sat(-ppB,   pw1B, t1B);                               \
            u2B = fma_sat(-base2B, pw2B, t2B);                              \
            _opB[_j * H_UNITS] = fmaf(pB, pw1B, basertB * pw2B);            \
        }                                                                   \
    } while (0)

#define WAITN()                                                             \
    do {                                                                    \
        asm volatile("cp.async.wait_group %0;" :: "n"(NCHUNK - 2)           \
                     : "memory");                                           \
        __syncwarp();                                                       \
    } while (0)

    // ---- Prologue: fill 7 of 8 ring chunks ----
#pragma unroll
    for (int c = 0; c < NCHUNK - 1; c++) {
        issue_chunk2(c, ld_pred, gA, gB, ringA, ringB, lane);
    }

    // ---- Peeled chunk 0 (SAFE body: u2 may exceed 1 pre-SAT) ----
    WAITN();
    issue_chunk2(NCHUNK - 1, ld_pred, gA, gB, ringA, ringB, lane);
    PROCESS2(0, 1);

    // ---- Steady state ----
    for (int c = 1; c < NCHUNKS_T - (NCHUNK - 1); c++) {
        WAITN();
        issue_chunk2(c + (NCHUNK - 1), ld_pred, gA, gB, ringA, ringB, lane);
        PROCESS2(c, 0);
    }

    // ---- Tail: last 7 chunks, all data resident ----
    asm volatile("cp.async.wait_group 0;" ::: "memory");
    __syncwarp();
    for (int c = NCHUNKS_T - (NCHUNK - 1); c < NCHUNKS_T; c++) {
        PROCESS2(c, 0);
    }

#undef WAITN
#undef PROCESS2
}

extern "C" void kernel_launch(void* const* d_in, const int* in_sizes, int n_in,
                              void* d_out, int out_size)
{
    const float* forcing       = (const float*)d_in[0];
    const float* initial_state = (const float*)d_in[1];
    const float* raw_params    = (const float*)d_in[2];
    const float* param_lower   = (const float*)d_in[3];
    const float* param_upper   = (const float*)d_in[4];
    float* out = (float*)d_out;

    fuse_scan_kernel<<<H_HALF / 32, 32>>>(forcing, initial_state, raw_params,
                                          param_lower, param_upper, out);
}

// round 10
// speedup vs baseline: 1.2878x; 1.2878x over previous
#include <cuda_runtime.h>
#include <cstdint>

// FUSE hydrology bucket model scan — fully software-pipelined: cp.async
// issue, LDS staging, and stores are interleaved into the MUFU chain's
// stall shadows instead of being front-loaded per chunk.
//
// forcing: (T,H,3) f32 (p=comp0, pet=comp1); out runoff: (T,H) f32.
// H=4096 units = 128 warps, one per SM; 1 unit per thread (optimal:
// measured step_cost ~ 75 + 19*N per-thread-unit).
// Carried chain: FFMA.SAT -> LG2 -> FMUL -> FMNMX -> EX2 -> FFMA.SAT.

#define T_STEPS   8192
#define H_UNITS   4096
#define H3        (H_UNITS * 3)
#define LG2EPS    (-19.931568569324174f)   // log2(1e-6)
#define CHUNK     8
#define NCHUNK    8
#define NCHUNKS_T (T_STEPS / CHUNK)        // 1024
#define SLOT_F    96                       // floats per step slot (32 x 3)

__device__ __forceinline__ float fast_lg2(float x) {
    float r;
    asm("lg2.approx.f32 %0, %1;" : "=f"(r) : "f"(x));
    return r;
}
__device__ __forceinline__ float fast_ex2(float x) {
    float r;
    asm("ex2.approx.f32 %0, %1;" : "=f"(r) : "f"(x));
    return r;
}
__device__ __forceinline__ float fma_sat(float a, float b, float c) {
    float r;
    asm("fma.rn.sat.f32 %0, %1, %2, %3;" : "=f"(r) : "f"(a), "f"(b), "f"(c));
    return r;
}

// One 16B cp.async for (chunk C, step J) — issued inside step bodies.
__device__ __forceinline__ void issue_one(int C, int J, bool ld_pred,
                                          const float* gwarp,
                                          unsigned ring_u32, int lane)
{
    if (ld_pred) {
        unsigned dst = ring_u32
            + (unsigned)(((C & (NCHUNK - 1)) * CHUNK + J) * (SLOT_F * 4))
            + (unsigned)lane * 16u;
        const float* src = gwarp + (size_t)(C * CHUNK + J) * H3 + lane * 4;
        asm volatile("cp.async.cg.shared.global [%0], [%1], 16;"
                     :: "r"(dst), "l"(src) : "memory");
    }
}

// Full-chunk burst (prologue only).
__device__ __forceinline__ void issue_chunk(int c, bool ld_pred,
                                            const float* gwarp,
                                            unsigned ring_u32, int lane)
{
#pragma unroll
    for (int j = 0; j < CHUNK; j++)
        issue_one(c, j, ld_pred, gwarp, ring_u32, lane);
    asm volatile("cp.async.commit_group;" ::: "memory");
}

__global__ void __launch_bounds__(32, 1)
fuse_scan_kernel(const float* __restrict__ forcing,
                 const float* __restrict__ initial_state,
                 const float* __restrict__ raw_params,
                 const float* __restrict__ param_lower,
                 const float* __restrict__ param_upper,
                 float* __restrict__ out)
{
    __shared__ float ring[NCHUNK * CHUNK * SLOT_F];   // 24 KB

    const int lane = threadIdx.x;
    const int h0   = blockIdx.x * 32;
    const int h    = h0 + lane;
    const bool ld_pred = (lane < 24);

    const unsigned ring_u32 = (unsigned)__cvta_generic_to_shared(ring);

    // ---- Parameter transform (once per unit, accurate expf) ----
    float phys[6];
#pragma unroll
    for (int i = 0; i < 6; i++) {
        float r  = raw_params[h * 6 + i];
        float s  = 1.0f / (1.0f + expf(-r));
        float lo = param_lower[i];
        float hi = param_upper[i];
        phys[i]  = lo + (hi - lo) * s;
    }
    const float inv_m1   = 1.0f / phys[0];
    const float inv_m2   = 1.0f / phys[1];
    const float baserte  = phys[3];
    const float qbp      = phys[4];
    const float bexp     = phys[5];
    const float perc2    = phys[2] * inv_m2;
    const float base2    = baserte * inv_m2;
    const float blo1     = bexp * LG2EPS;
    const float blo2     = qbp  * LG2EPS;
    const float om_perc1 = 1.0f - phys[2] * inv_m1;

    float u1 = initial_state[h * 2 + 0] * inv_m1;
    float u2 = initial_state[h * 2 + 1] * inv_m2;   // may exceed 1 at t=0

    const float* gwarp = forcing + (size_t)h0 * 3;

    // Double staging banks.
    float pb0[CHUNK], eb0[CHUNK], pb1[CHUNK], eb1[CHUNK];

    // CHUNK_BODY(C): wait; then 8 steps, each interleaving
    //   - chain heads (lg2)
    //   - 1 cp.async for chunk C+7 (if IOF)
    //   - LDS staging of chunk C+1 into (SP,SE) (if STF)
    //   - off-chain FFMA prep; chain tail; store.
#define CHUNK_BODY(C, RP, RE, SP, SE, SAFE, IOF, STF)                       \
    do {                                                                    \
        asm volatile("cp.async.wait_group %0;" :: "n"(5) : "memory");       \
        __syncwarp();                                                       \
        float* _op = out + (size_t)(C) * CHUNK * H_UNITS + h;               \
        const float* _st = ring                                             \
            + ((((C) + 1) & (NCHUNK - 1)) * CHUNK) * SLOT_F + lane * 3;     \
        _Pragma("unroll")                                                   \
        for (int _j = 0; _j < CHUNK; _j++) {                                \
            const float _l1 = fast_lg2(u1);                                 \
            const float _x2 = (SAFE) ? fminf(u2, 1.0f) : u2;                \
            const float _l2 = fast_lg2(_x2);                                \
            if (IOF) issue_one((C) + NCHUNK - 1, _j, ld_pred, gwarp,        \
                               ring_u32, lane);                             \
            if (STF) {                                                      \
                SP[_j] = _st[_j * SLOT_F + 0];                              \
                SE[_j] = _st[_j * SLOT_F + 1];                              \
            }                                                               \
            const float _p   = RP[_j];                                      \
            const float _pp  = _p * inv_m1;                                 \
            const float _omc = fmaf(-RE[_j], inv_m1, om_perc1);             \
            const float _t1  = fmaf(u1, _omc, _pp);                         \
            const float _t2  = fmaf(perc2, u1, u2);                         \
            const float _pw1 = fast_ex2(fmaxf(bexp * _l1, blo1));           \
            const float _pw2 = fast_ex2(fmaxf(qbp  * _l2, blo2));           \
            u1 = fma_sat(-_pp,   _pw1, _t1);                                \
            u2 = fma_sat(-base2, _pw2, _t2);                                \
            _op[_j * H_UNITS] = fmaf(_p, _pw1, baserte * _pw2);             \
        }                                                                   \
        if (IOF) asm volatile("cp.async.commit_group;" ::: "memory");       \
    } while (0)

#define STAGE_DIRECT(SP, SE, C)                                             \
    do {                                                                    \
        const float* _sd = ring                                             \
            + (((C) & (NCHUNK - 1)) * CHUNK) * SLOT_F + lane * 3;           \
        _Pragma("unroll")                                                   \
        for (int _j = 0; _j < CHUNK; _j++) {                                \
            SP[_j] = _sd[_j * SLOT_F + 0];                                  \
            SE[_j] = _sd[_j * SLOT_F + 1];                                  \
        }                                                                   \
    } while (0)

    // ---- Prologue: burst-issue chunks 0..6; stage chunk 0 ----
#pragma unroll
    for (int c = 0; c < NCHUNK - 1; c++)
        issue_chunk(c, ld_pred, gwarp, ring_u32, lane);

    asm volatile("cp.async.wait_group %0;" :: "n"(5) : "memory");
    __syncwarp();
    STAGE_DIRECT(pb0, eb0, 0);

    // ---- Peeled chunk 0 (SAFE: u2 may exceed 1 pre-SAT) ----
    CHUNK_BODY(0, pb0, eb0, pb1, eb1, 1, 1, 1);

    // ---- Main loop: pairs (odd, even), banks alternate ----
    // c = 1,3,...,1015; processes chunks 1..1016, stages 2..1017,
    // issues chunks 8..1023.
    for (int c = 1; c < NCHUNKS_T - NCHUNK + 1; c += 2) {
        CHUNK_BODY(c,     pb1, eb1, pb0, eb0, 0, 1, 1);
        CHUNK_BODY(c + 1, pb0, eb0, pb1, eb1, 0, 1, 1);
    }
    // After loop: processed through 1016, chunk 1017 staged in bank1,
    // all 1024 chunks issued.

    // ---- Epilogue ----
    asm volatile("cp.async.wait_group %0;" :: "n"(0) : "memory");
    __syncwarp();
    CHUNK_BODY(NCHUNKS_T - NCHUNK + 1, pb1, eb1, pb0, eb0, 0, 0, 0); // 1017
    for (int c = NCHUNKS_T - NCHUNK + 2; c < NCHUNKS_T; c++) {       // 1018..1023
        STAGE_DIRECT(pb0, eb0, c);
        CHUNK_BODY(c, pb0, eb0, pb1, eb1, 0, 0, 0);
    }

#undef STAGE_DIRECT
#undef CHUNK_BODY
}

extern "C" void kernel_launch(void* const* d_in, const int* in_sizes, int n_in,
                              void* d_out, int out_size)
{
    const float* forcing       = (const float*)d_in[0];
    const float* initial_state = (const float*)d_in[1];
    const float* raw_params    = (const float*)d_in[2];
    const float* param_lower   = (const float*)d_in[3];
    const float* param_upper   = (const float*)d_in[4];
    float* out = (float*)d_out;

    fuse_scan_kernel<<<H_UNITS / 32, 32>>>(forcing, initial_state, raw_params,
                                           param_lower, param_upper, out);
}

// round 11
// speedup vs baseline: 1.3194x; 1.0246x over previous
#include <cuda_runtime.h>
#include <cstdint>

// FUSE hydrology bucket model scan — modulo-scheduled step body: the
// EX2 results (pw1, pw2) are carried across iterations so that each
// step's chain tail (fma_sat) is immediately followed by the next
// step's chain head (lg2); stores, cp.async and staging issue inside
// the MUFU shadows.
//
// forcing: (T,H,3) f32 (p=comp0, pet=comp1); out runoff: (T,H) f32.
// H=4096 units = 128 warps, one per SM, 1 unit/thread.
// Carried chain: FFMA.SAT -> LG2 -> FMUL -> FMNMX -> EX2 -> FFMA.SAT.

#define T_STEPS   8192
#define H_UNITS   4096
#define H3        (H_UNITS * 3)
#define LG2EPS    (-19.931568569324174f)   // log2(1e-6)
#define CHUNK     8
#define NCHUNK    8
#define NCHUNKS_T (T_STEPS / CHUNK)        // 1024
#define SLOT_F    96                       // floats per step slot (32 x 3)

__device__ __forceinline__ float fast_lg2(float x) {
    float r;
    asm("lg2.approx.f32 %0, %1;" : "=f"(r) : "f"(x));
    return r;
}
__device__ __forceinline__ float fast_ex2(float x) {
    float r;
    asm("ex2.approx.f32 %0, %1;" : "=f"(r) : "f"(x));
    return r;
}
__device__ __forceinline__ float fma_sat(float a, float b, float c) {
    float r;
    asm("fma.rn.sat.f32 %0, %1, %2, %3;" : "=f"(r) : "f"(a), "f"(b), "f"(c));
    return r;
}

// One 16B cp.async for (chunk C, step J) — issued inside step bodies.
__device__ __forceinline__ void issue_one(int C, int J, bool ld_pred,
                                          const float* gwarp,
                                          unsigned ring_u32, int lane)
{
    if (ld_pred) {
        unsigned dst = ring_u32
            + (unsigned)(((C & (NCHUNK - 1)) * CHUNK + J) * (SLOT_F * 4))
            + (unsigned)lane * 16u;
        const float* src = gwarp + (size_t)(C * CHUNK + J) * H3 + lane * 4;
        asm volatile("cp.async.cg.shared.global [%0], [%1], 16;"
                     :: "r"(dst), "l"(src) : "memory");
    }
}

// Full-chunk burst (prologue only).
__device__ __forceinline__ void issue_chunk(int c, bool ld_pred,
                                            const float* gwarp,
                                            unsigned ring_u32, int lane)
{
#pragma unroll
    for (int j = 0; j < CHUNK; j++)
        issue_one(c, j, ld_pred, gwarp, ring_u32, lane);
    asm volatile("cp.async.commit_group;" ::: "memory");
}

__global__ void __launch_bounds__(32, 1)
fuse_scan_kernel(const float* __restrict__ forcing,
                 const float* __restrict__ initial_state,
                 const float* __restrict__ raw_params,
                 const float* __restrict__ param_lower,
                 const float* __restrict__ param_upper,
                 float* __restrict__ out)
{
    __shared__ float ring[NCHUNK * CHUNK * SLOT_F];   // 24 KB

    const int lane = threadIdx.x;
    const int h0   = blockIdx.x * 32;
    const int h    = h0 + lane;
    const bool ld_pred = (lane < 24);

    const unsigned ring_u32 = (unsigned)__cvta_generic_to_shared(ring);

    // ---- Parameter transform (once per unit, accurate expf) ----
    float phys[6];
#pragma unroll
    for (int i = 0; i < 6; i++) {
        float r  = raw_params[h * 6 + i];
        float s  = 1.0f / (1.0f + expf(-r));
        float lo = param_lower[i];
        float hi = param_upper[i];
        phys[i]  = lo + (hi - lo) * s;
    }
    const float inv_m1   = 1.0f / phys[0];
    const float inv_m2   = 1.0f / phys[1];
    const float baserte  = phys[3];
    const float qbp      = phys[4];
    const float bexp     = phys[5];
    const float perc2    = phys[2] * inv_m2;
    const float base2    = baserte * inv_m2;
    const float blo1     = bexp * LG2EPS;
    const float blo2     = qbp  * LG2EPS;
    const float om_perc1 = 1.0f - phys[2] * inv_m1;

    float u1 = initial_state[h * 2 + 0] * inv_m1;
    float u2 = initial_state[h * 2 + 1] * inv_m2;   // may exceed 1 at t=0

    // Pipeline prologue: powers of the INITIAL state. The u2>1 case
    // (s2_init may exceed m2) is clamped only here; afterwards u2 comes
    // from fma_sat and is always <= 1.
    float pw1 = fast_ex2(fmaxf(bexp * fast_lg2(u1),             blo1));
    float pw2 = fast_ex2(fmaxf(qbp  * fast_lg2(fminf(u2, 1.0f)), blo2));

    const float* gwarp = forcing + (size_t)h0 * 3;

    // Double staging banks.
    float pb0[CHUNK], eb0[CHUNK], pb1[CHUNK], eb1[CHUNK];

    // Modulo-scheduled chunk body. Entering each step: (u1,u2) = state,
    // (pw1,pw2) = powers of that state. Order puts fma_sat -> lg2
    // adjacent; stores/copies/staging live in the MUFU shadows.
#define CHUNK_BODY(C, RP, RE, SP, SE, IOF, STF)                             \
    do {                                                                    \
        asm volatile("cp.async.wait_group %0;" :: "n"(5) : "memory");       \
        __syncwarp();                                                       \
        float* _op = out + (size_t)(C) * CHUNK * H_UNITS + h;               \
        const float* _st = ring                                             \
            + ((((C) + 1) & (NCHUNK - 1)) * CHUNK) * SLOT_F + lane * 3;     \
        _Pragma("unroll")                                                   \
        for (int _j = 0; _j < CHUNK; _j++) {                                \
            const float _p   = RP[_j];                                      \
            const float _pp  = _p * inv_m1;                                 \
            const float _omc = fmaf(-RE[_j], inv_m1, om_perc1);             \
            const float _t1  = fmaf(u1, _omc, _pp);                         \
            const float _t2  = fmaf(perc2, u1, u2);                         \
            const float _run = fmaf(_p, pw1, baserte * pw2);                \
            u1 = fma_sat(-_pp,   pw1, _t1);                                 \
            u2 = fma_sat(-base2, pw2, _t2);                                 \
            const float _l1 = fast_lg2(u1);    /* next chain head */        \
            const float _l2 = fast_lg2(u2);                                 \
            _op[_j * H_UNITS] = _run;          /* in lg2 shadow */          \
            if (IOF) issue_one((C) + NCHUNK - 1, _j, ld_pred, gwarp,        \
                               ring_u32, lane);                             \
            if (STF) {                                                      \
                SP[_j] = _st[_j * SLOT_F + 0];                              \
                SE[_j] = _st[_j * SLOT_F + 1];                              \
            }                                                               \
            pw1 = fast_ex2(fmaxf(bexp * _l1, blo1));                        \
            pw2 = fast_ex2(fmaxf(qbp  * _l2, blo2));                        \
        }                                                                   \
        if (IOF) asm volatile("cp.async.commit_group;" ::: "memory");       \
    } while (0)

#define STAGE_DIRECT(SP, SE, C)                                             \
    do {                                                                    \
        const float* _sd = ring                                             \
            + (((C) & (NCHUNK - 1)) * CHUNK) * SLOT_F + lane * 3;           \
        _Pragma("unroll")                                                   \
        for (int _j = 0; _j < CHUNK; _j++) {                                \
            SP[_j] = _sd[_j * SLOT_F + 0];                                  \
            SE[_j] = _sd[_j * SLOT_F + 1];                                  \
        }                                                                   \
    } while (0)

    // ---- Prologue: burst-issue chunks 0..6; stage chunk 0 ----
#pragma unroll
    for (int c = 0; c < NCHUNK - 1; c++)
        issue_chunk(c, ld_pred, gwarp, ring_u32, lane);

    asm volatile("cp.async.wait_group %0;" :: "n"(5) : "memory");
    __syncwarp();
    STAGE_DIRECT(pb0, eb0, 0);

    // ---- Chunk 0 ----
    CHUNK_BODY(0, pb0, eb0, pb1, eb1, 1, 1);

    // ---- Main loop: pairs, banks alternate ----
    // c = 1,3,...,1015: processes chunks 1..1016, stages 2..1017,
    // issues chunks 8..1023.
    for (int c = 1; c < NCHUNKS_T - NCHUNK + 1; c += 2) {
        CHUNK_BODY(c,     pb1, eb1, pb0, eb0, 1, 1);
        CHUNK_BODY(c + 1, pb0, eb0, pb1, eb1, 1, 1);
    }

    // ---- Epilogue: chunks 1017..1023, all data resident ----
    asm volatile("cp.async.wait_group %0;" :: "n"(0) : "memory");
    __syncwarp();
    CHUNK_BODY(NCHUNKS_T - NCHUNK + 1, pb1, eb1, pb0, eb0, 0, 0); // 1017
    for (int c = NCHUNKS_T - NCHUNK + 2; c < NCHUNKS_T; c++) {    // 1018..1023
        STAGE_DIRECT(pb0, eb0, c);
        CHUNK_BODY(c, pb0, eb0, pb1, eb1, 0, 0);
    }

#undef STAGE_DIRECT
#undef CHUNK_BODY
}

extern "C" void kernel_launch(void* const* d_in, const int* in_sizes, int n_in,
                              void* d_out, int out_size)
{
    const float* forcing       = (const float*)d_in[0];
    const float* initial_state = (const float*)d_in[1];
    const float* raw_params    = (const float*)d_in[2];
    const float* param_lower   = (const float*)d_in[3];
    const float* param_upper   = (const float*)d_in[4];
    float* out = (float*)d_out;

    fuse_scan_kernel<<<H_UNITS / 32, 32>>>(forcing, initial_state, raw_params,
                                           param_lower, param_upper, out);
}